// round 11
// baseline (speedup 1.0000x reference)
#include <cuda_runtime.h>
#include <cuda_bf16.h>
#include <math.h>
#include <stdint.h>

#define S_LEN   1024
#define D_MOD   1024
#define N_HEADS 16
#define HEAD_D  64
#define D_FF    4096
#define N_LAYERS 6
#define EPSF    1.1920929e-07f

// ---------------- scratch (static device globals: no allocation) ----------------
__device__ float g_x [S_LEN*D_MOD];
__device__ float g_x0[S_LEN*D_MOD];
__device__ float g_xl[S_LEN*D_MOD];
__device__ float g_q [S_LEN*D_MOD];
__device__ float g_k [S_LEN*D_MOD];
__device__ float g_v [S_LEN*D_MOD];
__device__ float g_v1[S_LEN*D_MOD];
__device__ float g_part[4*S_LEN*D_MOD];
__device__ unsigned char g_maskbuf[S_LEN*S_LEN];
__device__ float g_cosb[S_LEN*32];
__device__ float g_sinb[S_LEN*32];
__device__ int   g_cpad[S_LEN+1];

// pre-split activations (bf16 hi/lo)
__device__ __nv_bfloat16 g_xnh[S_LEN*D_MOD], g_xnl[S_LEN*D_MOD];
__device__ __nv_bfloat16 g_yh [S_LEN*D_MOD], g_yl [S_LEN*D_MOD];
__device__ __nv_bfloat16 g_hh [S_LEN*D_FF],  g_hl [S_LEN*D_FF];
// pre-split weights (bf16 hi/lo)
__device__ __nv_bfloat16 g_wqh[N_LAYERS*D_MOD*D_MOD], g_wql[N_LAYERS*D_MOD*D_MOD];
__device__ __nv_bfloat16 g_wkh[N_LAYERS*D_MOD*D_MOD], g_wkl[N_LAYERS*D_MOD*D_MOD];
__device__ __nv_bfloat16 g_wvh[N_LAYERS*D_MOD*D_MOD], g_wvl[N_LAYERS*D_MOD*D_MOD];
__device__ __nv_bfloat16 g_woh[N_LAYERS*D_MOD*D_MOD], g_wol[N_LAYERS*D_MOD*D_MOD];
__device__ __nv_bfloat16 g_wfh[N_LAYERS*D_FF*D_MOD],  g_wfl[N_LAYERS*D_FF*D_MOD];
__device__ __nv_bfloat16 g_wph[N_LAYERS*D_MOD*D_FF],  g_wpl[N_LAYERS*D_MOD*D_FF];

// ---------------- helpers ----------------
__device__ __forceinline__ uint32_t smem_u32(const void* p) {
    uint32_t a;
    asm("{ .reg .u64 t; cvta.to.shared.u64 t, %1; cvt.u32.u64 %0, t; }" : "=r"(a) : "l"(p));
    return a;
}

#define LDMATRIX_X4(r0, r1, r2, r3, addr) \
    asm volatile("ldmatrix.sync.aligned.m8n8.x4.shared.b16 {%0,%1,%2,%3}, [%4];" \
                 : "=r"(r0), "=r"(r1), "=r"(r2), "=r"(r3) : "r"(addr))

#define MMA_BF16(c, a, b) \
    asm volatile("mma.sync.aligned.m16n8k16.row.col.f32.bf16.bf16.f32 " \
                 "{%0,%1,%2,%3}, {%4,%5,%6,%7}, {%8,%9}, {%0,%1,%2,%3};" \
                 : "+f"((c)[0]), "+f"((c)[1]), "+f"((c)[2]), "+f"((c)[3]) \
                 : "r"((a)[0]), "r"((a)[1]), "r"((a)[2]), "r"((a)[3]), \
                   "r"((b)[0]), "r"((b)[1]))

#define CP16(dst, src) \
    asm volatile("cp.async.cg.shared.global [%0], [%1], 16;" :: "r"(dst), "l"(src))
#define CP_COMMIT() asm volatile("cp.async.commit_group;" ::: "memory")
#define CP_WAIT0()  asm volatile("cp.async.wait_group 0;" ::: "memory")
#define CP_WAIT1()  asm volatile("cp.async.wait_group 1;" ::: "memory")

__device__ __forceinline__ uint32_t bf2u(__nv_bfloat162 h) {
    return *reinterpret_cast<uint32_t*>(&h);
}

__device__ __forceinline__ void split4(float4 v, uint2& hi, uint2& lo) {
    __nv_bfloat162 h01 = __floats2bfloat162_rn(v.x, v.y);
    __nv_bfloat162 h23 = __floats2bfloat162_rn(v.z, v.w);
    float lx = v.x - __low2float(h01);
    float ly = v.y - __high2float(h01);
    float lz = v.z - __low2float(h23);
    float lw = v.w - __high2float(h23);
    hi = make_uint2(bf2u(h01), bf2u(h23));
    lo = make_uint2(bf2u(__floats2bfloat162_rn(lx, ly)), bf2u(__floats2bfloat162_rn(lz, lw)));
}

__device__ __forceinline__ void split2store(float a, float b,
                                            __nv_bfloat16* hi, __nv_bfloat16* lo, size_t idx) {
    __nv_bfloat162 h = __floats2bfloat162_rn(a, b);
    float la = a - __low2float(h), lb = b - __high2float(h);
    *(__nv_bfloat162*)(hi + idx) = h;
    *(__nv_bfloat162*)(lo + idx) = __floats2bfloat162_rn(la, lb);
}

__device__ __forceinline__ float block_sum(float v) {
    __shared__ float sh[32];
    int lane = threadIdx.x & 31, wid = threadIdx.x >> 5;
    #pragma unroll
    for (int o = 16; o; o >>= 1) v += __shfl_xor_sync(0xffffffffu, v, o);
    if (lane == 0) sh[wid] = v;
    __syncthreads();
    int nw = (blockDim.x + 31) >> 5;
    v = (lane < nw) ? sh[lane] : 0.f;
    #pragma unroll
    for (int o = 16; o; o >>= 1) v += __shfl_xor_sync(0xffffffffu, v, o);
    __syncthreads();
    return v;
}

// ---------------- setup kernels ----------------
__global__ void scan_levels(const int* __restrict__ levels, int* __restrict__ cpad) {
    __shared__ int sh[S_LEN];
    int t = threadIdx.x;
    sh[t] = (levels[t] == 0) ? 1 : 0;
    __syncthreads();
    for (int o = 1; o < S_LEN; o <<= 1) {
        int add = (t >= o) ? sh[t - o] : 0;
        __syncthreads();
        sh[t] += add;
        __syncthreads();
    }
    if (t == 0) cpad[0] = 0;
    cpad[t + 1] = sh[t];
}

__global__ void build_mask(const int* __restrict__ levels, const int* __restrict__ sample_idx,
                           const int* __restrict__ cpad, unsigned char* __restrict__ mask) {
    int i = blockIdx.x;
    int si = sample_idx[i];
    int ci = cpad[i];
    for (int j = threadIdx.x; j < S_LEN; j += blockDim.x) {
        bool causal = (i >= j);
        bool same   = (si == sample_idx[j]);
        int  cnt    = ci - cpad[j + 1];
        bool markov = (levels[j] == 0) && (cnt > 0);
        mask[(size_t)i * S_LEN + j] = (causal && same && !markov) ? 1 : 0;
    }
}

__global__ void rope_table(float* __restrict__ cosb, float* __restrict__ sinb) {
    int s = blockIdx.x;
    int e = threadIdx.x;
    float inv = powf(10000.f, -((float)e) / 32.f);
    float fr  = (float)s * inv;
    cosb[s * 32 + e] = cosf(fr);
    sinb[s * 32 + e] = sinf(fr);
}

__global__ void split_arr(const float4* __restrict__ src, uint2* __restrict__ hi,
                          uint2* __restrict__ lo, int n4) {
    int i = blockIdx.x * blockDim.x + threadIdx.x;
    if (i < n4) { uint2 h, l; split4(src[i], h, l); hi[i] = h; lo[i] = l; }
}

__global__ void reduce4k(const float4* __restrict__ part, const float4* __restrict__ res,
                         float4* __restrict__ out, int n4) {
    int i = blockIdx.x * blockDim.x + threadIdx.x;
    if (i >= n4) return;
    float4 a = part[i], b = part[i + n4], c = part[i + 2 * n4], d = part[i + 3 * n4];
    float4 r = res[i];
    out[i] = make_float4(r.x + a.x + b.x + c.x + d.x,
                         r.y + a.y + b.y + c.y + d.y,
                         r.z + a.z + b.z + c.z + d.z,
                         r.w + a.w + b.w + c.w + d.w);
}

// ---------------- row-wise rms ----------------
__global__ void rms_rows(const float* __restrict__ in, float* __restrict__ out) {
    int row = blockIdx.x, tid = threadIdx.x;
    float4 a = ((const float4*)(in + (size_t)row * D_MOD))[tid];
    float ss = a.x*a.x + a.y*a.y + a.z*a.z + a.w*a.w;
    ss = block_sum(ss);
    float r = rsqrtf(ss * (1.f / D_MOD) + EPSF);
    ((float4*)(out + (size_t)row * D_MOD))[tid] = make_float4(a.x*r, a.y*r, a.z*r, a.w*r);
}

__global__ void rms_b(const float* __restrict__ in,
                      __nv_bfloat16* __restrict__ oh, __nv_bfloat16* __restrict__ ol) {
    int row = blockIdx.x, tid = threadIdx.x;
    float4 a = ((const float4*)(in + (size_t)row * D_MOD))[tid];
    float ss = a.x*a.x + a.y*a.y + a.z*a.z + a.w*a.w;
    ss = block_sum(ss);
    float r = rsqrtf(ss * (1.f / D_MOD) + EPSF);
    size_t base = (size_t)row * D_MOD + tid * 4;
    split2store(a.x*r, a.y*r, oh, ol, base);
    split2store(a.z*r, a.w*r, oh, ol, base + 2);
}

__global__ void mix_rms(const float* __restrict__ x, const float* __restrict__ x0,
                        const float* __restrict__ lambdas, int layer,
                        float* __restrict__ xl,
                        __nv_bfloat16* __restrict__ xnh, __nv_bfloat16* __restrict__ xnl) {
    int row = blockIdx.x, tid = threadIdx.x;
    float l0 = lambdas[2 * layer], l1 = lambdas[2 * layer + 1];
    float4 a = ((const float4*)(x  + (size_t)row * D_MOD))[tid];
    float4 b = ((const float4*)(x0 + (size_t)row * D_MOD))[tid];
    float4 m = make_float4(l0*a.x + l1*b.x, l0*a.y + l1*b.y, l0*a.z + l1*b.z, l0*a.w + l1*b.w);
    float ss = m.x*m.x + m.y*m.y + m.z*m.z + m.w*m.w;
    ss = block_sum(ss);
    float r = rsqrtf(ss * (1.f / D_MOD) + EPSF);
    ((float4*)(xl + (size_t)row * D_MOD))[tid] = m;
    size_t base = (size_t)row * D_MOD + tid * 4;
    split2store(m.x*r, m.y*r, xnh, xnl, base);
    split2store(m.z*r, m.w*r, xnh, xnl, base + 2);
}

// ================= pre-split bf16 HMMA GEMM, cp.async 2-stage =================
// epi: 0 = QKV (z selects B and fp32 C out), 2 = relu^2 -> bf16 hi/lo out,
//      4 = split-K partial fp32 (z = K-slice of 4, Cf0 base)
#define GSK    40
#define TILE_B (128 * GSK * 2)       // 10240 B
#define STAGE_B (4 * TILE_B)         // 40960 B
#define GEMM_SMEM (2 * STAGE_B)      // 81920 B

__global__ __launch_bounds__(256, 1)
void gemm_bf16(const __nv_bfloat16* __restrict__ Ah, const __nv_bfloat16* __restrict__ Al,
               const __nv_bfloat16* __restrict__ Bh0, const __nv_bfloat16* __restrict__ Bl0,
               const __nv_bfloat16* __restrict__ Bh1, const __nv_bfloat16* __restrict__ Bl1,
               const __nv_bfloat16* __restrict__ Bh2, const __nv_bfloat16* __restrict__ Bl2,
               float* __restrict__ Cf0, float* __restrict__ Cf1, float* __restrict__ Cf2,
               __nv_bfloat16* __restrict__ Chh, __nv_bfloat16* __restrict__ Chl,
               int N, int K, int epi)
{
    extern __shared__ char smem[];
    uint32_t sbase = smem_u32(smem);

    int tid = threadIdx.x, wid = tid >> 5, lane = tid & 31;
    int wm = wid & 3, wn = wid >> 2;
    int z = blockIdx.z;
    int row0 = blockIdx.y * 128, col0 = blockIdx.x * 128;
    int Ks    = (epi == 4) ? (K >> 2) : K;
    int kbase = (epi == 4) ? z * Ks : 0;
    int nch   = Ks >> 5;

    const __nv_bfloat16* Bh = Bh0;
    const __nv_bfloat16* Bl = Bl0;
    if (epi == 0) {
        if (z == 1) { Bh = Bh1; Bl = Bl1; }
        else if (z == 2) { Bh = Bh2; Bl = Bl2; }
    }

    float acc[2][8][4];
    #pragma unroll
    for (int mi = 0; mi < 2; ++mi)
        #pragma unroll
        for (int ni = 0; ni < 8; ++ni)
            #pragma unroll
            for (int e = 0; e < 4; ++e) acc[mi][ni][e] = 0.f;

    // cp.async stage issue: 4 tiles x 2 chunks(16B) per thread
    auto issue = [&](int c) {
        int k0 = kbase + (c << 5);
        uint32_t base = sbase + (uint32_t)((c & 1) * STAGE_B);
        #pragma unroll
        for (int i = 0; i < 2; ++i) {
            int q = tid + i * 256;
            int r = q >> 2, cc = q & 3;
            uint32_t d = base + (uint32_t)(r * (GSK * 2) + cc * 16);
            size_t aoff = (size_t)(row0 + r) * K + k0 + cc * 8;
            size_t boff = (size_t)(col0 + r) * K + k0 + cc * 8;
            CP16(d,              (const char*)(Ah + aoff));
            CP16(d + TILE_B,     (const char*)(Al + aoff));
            CP16(d + 2 * TILE_B, (const char*)(Bh + boff));
            CP16(d + 3 * TILE_B, (const char*)(Bl + boff));
        }
        CP_COMMIT();
    };

    int a_r = wm * 32 + (lane & 15);
    int a_c = (lane >> 4) * 8;
    int b_r = wn * 64 + ((lane >> 4) & 1) * 8 + (lane & 7);
    int b_c = ((lane >> 3) & 1) * 8;

    issue(0);
    for (int c = 0; c < nch; ++c) {
        if (c + 1 < nch) { issue(c + 1); CP_WAIT1(); } else { CP_WAIT0(); }
        __syncthreads();

        uint32_t tb   = sbase + (uint32_t)((c & 1) * STAGE_B);
        uint32_t tAhi = tb, tAlo = tb + TILE_B;
        uint32_t tBhi = tb + 2 * TILE_B, tBlo = tb + 3 * TILE_B;

        #pragma unroll
        for (int ks = 0; ks < 2; ++ks) {
            uint32_t a_hi[2][4], a_lo[2][4];
            #pragma unroll
            for (int mi = 0; mi < 2; ++mi) {
                uint32_t off = (uint32_t)((a_r + mi * 16) * GSK + ks * 16 + a_c) * 2;
                LDMATRIX_X4(a_hi[mi][0], a_hi[mi][1], a_hi[mi][2], a_hi[mi][3], tAhi + off);
                LDMATRIX_X4(a_lo[mi][0], a_lo[mi][1], a_lo[mi][2], a_lo[mi][3], tAlo + off);
            }
            uint32_t b_hi[8][2], b_lo[8][2];
            #pragma unroll
            for (int p = 0; p < 4; ++p) {
                uint32_t off = (uint32_t)((b_r + p * 16) * GSK + ks * 16 + b_c) * 2;
                LDMATRIX_X4(b_hi[2*p][0], b_hi[2*p][1], b_hi[2*p+1][0], b_hi[2*p+1][1], tBhi + off);
                LDMATRIX_X4(b_lo[2*p][0], b_lo[2*p][1], b_lo[2*p+1][0], b_lo[2*p+1][1], tBlo + off);
            }
            #pragma unroll
            for (int mi = 0; mi < 2; ++mi)
                #pragma unroll
                for (int ni = 0; ni < 8; ++ni) {
                    MMA_BF16(acc[mi][ni], a_hi[mi], b_hi[ni]);
                    MMA_BF16(acc[mi][ni], a_hi[mi], b_lo[ni]);
                    MMA_BF16(acc[mi][ni], a_lo[mi], b_hi[ni]);
                }
        }
        __syncthreads();
    }

    if (epi == 4) {
        float* Cz = Cf0 + (size_t)z * S_LEN * N;
        #pragma unroll
        for (int mi = 0; mi < 2; ++mi)
            #pragma unroll
            for (int ni = 0; ni < 8; ++ni) {
                int row = row0 + wm * 32 + mi * 16 + (lane >> 2);
                int col = col0 + wn * 64 + ni * 8 + (lane & 3) * 2;
                *(float2*)&Cz[(size_t)row * N + col] =
                    make_float2(acc[mi][ni][0], acc[mi][ni][1]);
                *(float2*)&Cz[(size_t)(row + 8) * N + col] =
                    make_float2(acc[mi][ni][2], acc[mi][ni][3]);
            }
    } else if (epi == 2) {
        #pragma unroll
        for (int mi = 0; mi < 2; ++mi)
            #pragma unroll
            for (int ni = 0; ni < 8; ++ni)
                #pragma unroll
                for (int half = 0; half < 2; ++half) {
                    int row = row0 + wm * 32 + mi * 16 + half * 8 + (lane >> 2);
                    int col = col0 + wn * 64 + ni * 8 + (lane & 3) * 2;
                    float v0 = acc[mi][ni][half * 2], v1 = acc[mi][ni][half * 2 + 1];
                    v0 = v0 > 0.f ? v0 * v0 : 0.f;
                    v1 = v1 > 0.f ? v1 * v1 : 0.f;
                    split2store(v0, v1, Chh, Chl, (size_t)row * N + col);
                }
    } else { // epi == 0: plain fp32 out, z selects C
        float* C = (z == 0) ? Cf0 : (z == 1) ? Cf1 : Cf2;
        #pragma unroll
        for (int mi = 0; mi < 2; ++mi)
            #pragma unroll
            for (int ni = 0; ni < 8; ++ni) {
                int row = row0 + wm * 32 + mi * 16 + (lane >> 2);
                int col = col0 + wn * 64 + ni * 8 + (lane & 3) * 2;
                *(float2*)&C[(size_t)row * N + col] =
                    make_float2(acc[mi][ni][0], acc[mi][ni][1]);
                *(float2*)&C[(size_t)(row + 8) * N + col] =
                    make_float2(acc[mi][ni][2], acc[mi][ni][3]);
            }
    }
}

// ---------------- value residual blend ----------------
__global__ void v_blend(float* __restrict__ v, float* __restrict__ v1,
                        const float* __restrict__ lamb, int layer) {
    int i = blockIdx.x * blockDim.x + threadIdx.x;
    float lm = lamb[layer];
    float4* v4  = (float4*)v;
    float4* v14 = (float4*)v1;
    float4 a = v4[i];
    float4 b;
    if (layer == 0) { v14[i] = a; b = a; } else { b = v14[i]; }
    float om = 1.f - lm;
    v4[i] = make_float4(om*a.x + lm*b.x, om*a.y + lm*b.y, om*a.z + lm*b.z, om*a.w + lm*b.w);
}

// ---------------- per-head rms + rope on q and k ----------------
__global__ void qk_rms_rope(float* __restrict__ qb, float* __restrict__ kb,
                            const float* __restrict__ cosb, const float* __restrict__ sinb) {
    int pair = blockIdx.x * 8 + (threadIdx.x >> 5);
    int lane = threadIdx.x & 31;
    int s = pair >> 4;
    int h = pair & 15;
    float c  = cosb[s * 32 + lane];
    float si = sinb[s * 32 + lane];
    float* bufs[2] = { qb, kb };
    #pragma unroll
    for (int b = 0; b < 2; ++b) {
        float* p = bufs[b] + (size_t)s * D_MOD + h * HEAD_D;
        float x1 = p[lane];
        float x2 = p[lane + 32];
        float ss = x1 * x1 + x2 * x2;
        #pragma unroll
        for (int o = 16; o; o >>= 1) ss += __shfl_xor_sync(0xffffffffu, ss, o);
        float r = rsqrtf(ss * (1.f / HEAD_D) + EPSF);
        x1 *= r; x2 *= r;
        p[lane]      =  x1 * c  + x2 * si;
        p[lane + 32] = -x1 * si + x2 * c;
    }
}

// ================= fused flash attention (split-bf16 HMMA) =================
#define FQS 72
#define FVS 136
#define OFF_QHI 0
#define OFF_QLO (128*FQS*2)
#define OFF_KHI (2*128*FQS*2)
#define OFF_KLO (3*128*FQS*2)
#define OFF_VHI (4*128*FQS*2)
#define OFF_VLO (OFF_VHI + 64*FVS*2)
#define OFF_MSK (OFF_VLO + 64*FVS*2)
#define FLASH_SMEM (OFF_MSK + 128*128)

__global__ __launch_bounds__(256, 1)
void flash_attn(const float* __restrict__ q, const float* __restrict__ k,
                const float* __restrict__ v, const unsigned char* __restrict__ mask,
                __nv_bfloat16* __restrict__ yh, __nv_bfloat16* __restrict__ yl)
{
    extern __shared__ char fs[];
    uint32_t sb = smem_u32(fs);

    int qb = blockIdx.x;
    int h  = blockIdx.y;
    int q0 = qb * 128;
    int tid = threadIdx.x, lane = tid & 31, w = tid >> 5;

    #pragma unroll
    for (int i = 0; i < 8; ++i) {
        int f = tid + i * 256;
        int r = f >> 4, c4 = f & 15;
        float4 a = *(const float4*)&q[(size_t)(q0 + r) * D_MOD + h * HEAD_D + c4 * 4];
        uint2 hi, lo;
        split4(a, hi, lo);
        uint32_t off = (uint32_t)(r * FQS + c4 * 4) * 2;
        *(uint2*)(fs + OFF_QHI + off) = hi;
        *(uint2*)(fs + OFF_QLO + off) = lo;
    }

    float m0 = -3.4e38f, m1 = -3.4e38f, l0 = 0.f, l1 = 0.f;
    float oacc[8][4];
    #pragma unroll
    for (int nj = 0; nj < 8; ++nj)
        #pragma unroll
        for (int e = 0; e < 4; ++e) oacc[nj][e] = 0.f;

    int aq_off = (w * 16 + (lane & 15)) * FQS + (lane >> 4) * 8;
    int bk_r   = ((lane >> 4) & 1) * 8 + (lane & 7);
    int bk_c   = ((lane >> 3) & 1) * 8;
    int rowm   = w * 16 + (lane >> 2);

    for (int kb = 0; kb <= qb; ++kb) {
        if (kb > 0) __syncthreads();
        #pragma unroll
        for (int i = 0; i < 8; ++i) {
            int f = tid + i * 256;
            int r = f >> 4, c4 = f & 15;
            float4 a = *(const float4*)&k[(size_t)(kb * 128 + r) * D_MOD + h * HEAD_D + c4 * 4];
            uint2 hi, lo;
            split4(a, hi, lo);
            uint32_t off = (uint32_t)(r * FQS + c4 * 4) * 2;
            *(uint2*)(fs + OFF_KHI + off) = hi;
            *(uint2*)(fs + OFF_KLO + off) = lo;

            float4 b = *(const float4*)&v[(size_t)(kb * 128 + r) * D_MOD + h * HEAD_D + c4 * 4];
            float bb[4] = { b.x, b.y, b.z, b.w };
            #pragma unroll
            for (int j = 0; j < 4; ++j) {
                __nv_bfloat16 hb = __float2bfloat16_rn(bb[j]);
                __nv_bfloat16 lb = __float2bfloat16_rn(bb[j] - __bfloat162float(hb));
                uint32_t to = (uint32_t)((c4 * 4 + j) * FVS + r) * 2;
                *(__nv_bfloat16*)(fs + OFF_VHI + to) = hb;
                *(__nv_bfloat16*)(fs + OFF_VLO + to) = lb;
            }
        }
        #pragma unroll
        for (int i = 0; i < 4; ++i) {
            int idx = tid + i * 256;
            int r = idx >> 3, c16 = idx & 7;
            uint4 mm = *(const uint4*)&mask[(size_t)(q0 + r) * S_LEN + kb * 128 + c16 * 16];
            *(uint4*)(fs + OFF_MSK + r * 128 + c16 * 16) = mm;
        }
        __syncthreads();

        float sacc[16][4];
        #pragma unroll
        for (int nf = 0; nf < 16; ++nf)
            #pragma unroll
            for (int e = 0; e < 4; ++e) sacc[nf][e] = 0.f;

        #pragma unroll
        for (int kc = 0; kc < 4; ++kc) {
            uint32_t ah[4], al[4];
            uint32_t aoff = (uint32_t)(aq_off + kc * 16) * 2;
            LDMATRIX_X4(ah[0], ah[1], ah[2], ah[3], sb + OFF_QHI + aoff);
            LDMATRIX_X4(al[0], al[1], al[2], al[3], sb + OFF_QLO + aoff);
            #pragma unroll
            for (int np = 0; np < 8; ++np) {
                uint32_t bh[2][2], bl[2][2];
                uint32_t boff = (uint32_t)((bk_r + np * 16) * FQS + bk_c + kc * 16) * 2;
                LDMATRIX_X4(bh[0][0], bh[0][1], bh[1][0], bh[1][1], sb + OFF_KHI + boff);
                LDMATRIX_X4(bl[0][0], bl[0][1], bl[1][0], bl[1][1], sb + OFF_KLO + boff);
                #pragma unroll
                for (int u = 0; u < 2; ++u) {
                    MMA_BF16(sacc[2*np+u], ah, bh[u]);
                    MMA_BF16(sacc[2*np+u], ah, bl[u]);
                    MMA_BF16(sacc[2*np+u], al, bh[u]);
                }
            }
        }

        float rmax0 = -3.4e38f, rmax1 = -3.4e38f;
        #pragma unroll
        for (int nf = 0; nf < 16; ++nf) {
            int colp = nf * 8 + (lane & 3) * 2;
            unsigned short mm0 = *(const unsigned short*)(fs + OFF_MSK + rowm * 128 + colp);
            unsigned short mm1 = *(const unsigned short*)(fs + OFF_MSK + (rowm + 8) * 128 + colp);
            sacc[nf][0] = (mm0 & 0xff)   ? sacc[nf][0] * 0.125f : -1e30f;
            sacc[nf][1] = (mm0 & 0xff00) ? sacc[nf][1] * 0.125f : -1e30f;
            sacc[nf][2] = (mm1 & 0xff)   ? sacc[nf][2] * 0.125f : -1e30f;
            sacc[nf][3] = (mm1 & 0xff00) ? sacc[nf][3] * 0.125f : -1e30f;
            rmax0 = fmaxf(rmax0, fmaxf(sacc[nf][0], sacc[nf][1]));
            rmax1 = fmaxf(rmax1, fmaxf(sacc[nf][2], sacc[nf][3]));
        }
        rmax0 = fmaxf(rmax0, __shfl_xor_sync(0xffffffffu, rmax0, 1));
        rmax0 = fmaxf(rmax0, __shfl_xor_sync(0xffffffffu, rmax0, 2));
        rmax1 = fmaxf(rmax1, __shfl_xor_sync(0xffffffffu, rmax1, 1));
        rmax1 = fmaxf(rmax1, __shfl_xor_sync(0xffffffffu, rmax1, 2));

        float mn0 = fmaxf(m0, rmax0), mn1 = fmaxf(m1, rmax1);
        float sc0 = __expf(m0 - mn0), sc1 = __expf(m1 - mn1);
        float sum0 = 0.f, sum1 = 0.f;
        #pragma unroll
        for (int nf = 0; nf < 16; ++nf) {
            sacc[nf][0] = __expf(sacc[nf][0] - mn0);
            sacc[nf][1] = __expf(sacc[nf][1] - mn0);
            sacc[nf][2] = __expf(sacc[nf][2] - mn1);
            sacc[nf][3] = __expf(sacc[nf][3] - mn1);
            sum0 += sacc[nf][0] + sacc[nf][1];
            sum1 += sacc[nf][2] + sacc[nf][3];
        }
        sum0 += __shfl_xor_sync(0xffffffffu, sum0, 1);
        sum0 += __shfl_xor_sync(0xffffffffu, sum0, 2);
        sum1 += __shfl_xor_sync(0xffffffffu, sum1, 1);
        sum1 += __shfl_xor_sync(0xffffffffu, sum1, 2);
        l0 = l0 * sc0 + sum0;
        l1 = l1 * sc1 + sum1;
        m0 = mn0; m1 = mn1;
        #pragma unroll
        for (int nj = 0; nj < 8; ++nj) {
            oacc[nj][0] *= sc0; oacc[nj][1] *= sc0;
            oacc[nj][2] *= sc1; oacc[nj][3] *= sc1;
        }

        #pragma unroll
        for (int kc = 0; kc < 8; ++kc) {
            uint32_t ph[4], pl[4];
            #pragma unroll
            for (int u = 0; u < 2; ++u) {
                float p0 = sacc[2*kc + u][0], p1 = sacc[2*kc + u][1];
                float p2 = sacc[2*kc + u][2], p3 = sacc[2*kc + u][3];
                __nv_bfloat162 h01 = __floats2bfloat162_rn(p0, p1);
                __nv_bfloat162 h23 = __floats2bfloat162_rn(p2, p3);
                ph[u * 2 + 0] = bf2u(h01);
                ph[u * 2 + 1] = bf2u(h23);
                pl[u * 2 + 0] = bf2u(__floats2bfloat162_rn(p0 - __low2float(h01), p1 - __high2float(h01)));
                pl[u * 2 + 1] = bf2u(__floats2bfloat162_rn(p2 - __low2float(h23), p3 - __high2float(h23)));
            }
            uint32_t ah[4] = { ph[0], ph[1], ph[2], ph[3] };
            uint32_t al[4] = { pl[0], pl[1], pl[2], pl[3] };
            #pragma unroll
            for (int np = 0; np < 4; ++np) {
                uint32_t bh[2][2], bl[2][2];
                uint32_t boff = (uint32_t)((bk_r + np * 16) * FVS + bk_c + kc * 16) * 2;
                LDMATRIX_X4(bh[0][0], bh[0][1], bh[1][0], bh[1][1], sb + OFF_VHI + boff);
                LDMATRIX_X4(bl[0][0], bl[0][1], bl[1][0], bl[1][1], sb + OFF_VLO + boff);
                #pragma unroll
                for (int u = 0; u < 2; ++u) {
                    MMA_BF16(oacc[2*np+u], ah, bh[u]);
                    MMA_BF16(oacc[2*np+u], ah, bl[u]);
                    MMA_BF16(oacc[2*np+u], al, bh[u]);
                }
            }
        }
    }

    float inv0 = 1.f / l0, inv1 = 1.f / l1;
    #pragma unroll
    for (int nj = 0; nj < 8; ++nj) {
        int row = q0 + rowm;
        int col = h * HEAD_D + nj * 8 + (lane & 3) * 2;
        split2store(oacc[nj][0] * inv0, oacc[nj][1] * inv0, yh, yl, (size_t)row * D_MOD + col);
        split2store(oacc[nj][2] * inv1, oacc[nj][3] * inv1, yh, yl, (size_t)(row + 8) * D_MOD + col);
    }
}

// ---------------- host ----------------
extern "C" void kernel_launch(void* const* d_in, const int* in_sizes, int n_in,
                              void* d_out, int out_size) {
    const float* x_in     = (const float*)d_in[0];
    const float* Wq       = (const float*)d_in[1];
    const float* Wk       = (const float*)d_in[2];
    const float* Wv       = (const float*)d_in[3];
    const float* Wo       = (const float*)d_in[4];
    const float* lamb     = (const float*)d_in[5];
    const float* lambdas  = (const float*)d_in[6];
    const float* Wfc      = (const float*)d_in[7];
    const float* Wp       = (const float*)d_in[8];
    const int*   levels   = (const int*)d_in[9];
    const int*   sample_i = (const int*)d_in[10];
    float* out = (float*)d_out;

    cudaFuncSetAttribute(gemm_bf16, cudaFuncAttributeMaxDynamicSharedMemorySize, GEMM_SMEM);
    cudaFuncSetAttribute(flash_attn, cudaFuncAttributeMaxDynamicSharedMemorySize, FLASH_SMEM);

    float *gx, *gx0, *gxl, *gq, *gk, *gv, *gv1, *gpart, *gcos, *gsin;
    unsigned char* gmask;
    int* gcpad;
    __nv_bfloat16 *xnh, *xnl, *yh, *yl, *hh, *hl;
    __nv_bfloat16 *wqh, *wql, *wkh, *wkl, *wvh, *wvl, *woh, *wol, *wfh, *wfl, *wph, *wpl;

    cudaGetSymbolAddress((void**)&gx,    g_x);
    cudaGetSymbolAddress((void**)&gx0,   g_x0);
    cudaGetSymbolAddress((void**)&gxl,   g_xl);
    cudaGetSymbolAddress((void**)&gq,    g_q);
    cudaGetSymbolAddress((void**)&gk,    g_k);
    cudaGetSymbolAddress((void**)&gv,    g_v);
    cudaGetSymbolAddress((void**)&gv1,   g_v1);
    cudaGetSymbolAddress((void**)&gpart, g_part);
    cudaGetSymbolAddress((void**)&gmask, g_maskbuf);
    cudaGetSymbolAddress((void**)&gcos,  g_cosb);
    cudaGetSymbolAddress((void**)&gsin,  g_sinb);
    cudaGetSymbolAddress((void**)&gcpad, g_cpad);
    cudaGetSymbolAddress((void**)&xnh,   g_xnh);
    cudaGetSymbolAddress((void**)&xnl,   g_xnl);
    cudaGetSymbolAddress((void**)&yh,    g_yh);
    cudaGetSymbolAddress((void**)&yl,    g_yl);
    cudaGetSymbolAddress((void**)&hh,    g_hh);
    cudaGetSymbolAddress((void**)&hl,    g_hl);
    cudaGetSymbolAddress((void**)&wqh,   g_wqh);
    cudaGetSymbolAddress((void**)&wql,   g_wql);
    cudaGetSymbolAddress((void**)&wkh,   g_wkh);
    cudaGetSymbolAddress((void**)&wkl,   g_wkl);
    cudaGetSymbolAddress((void**)&wvh,   g_wvh);
    cudaGetSymbolAddress((void**)&wvl,   g_wvl);
    cudaGetSymbolAddress((void**)&woh,   g_woh);
    cudaGetSymbolAddress((void**)&wol,   g_wol);
    cudaGetSymbolAddress((void**)&wfh,   g_wfh);
    cudaGetSymbolAddress((void**)&wfl,   g_wfl);
    cudaGetSymbolAddress((void**)&wph,   g_wph);
    cudaGetSymbolAddress((void**)&wpl,   g_wpl);

    const int n4    = S_LEN * D_MOD / 4;
    const int nw4   = N_LAYERS * D_MOD * D_MOD / 4;   // 1.57M float4
    const int nwff4 = N_LAYERS * D_FF * D_MOD / 4;    // 6.29M float4

    // weight pre-split (runs each launch; deterministic)
    split_arr<<<(nw4 + 255) / 256, 256>>>((const float4*)Wq, (uint2*)wqh, (uint2*)wql, nw4);
    split_arr<<<(nw4 + 255) / 256, 256>>>((const float4*)Wk, (uint2*)wkh, (uint2*)wkl, nw4);
    split_arr<<<(nw4 + 255) / 256, 256>>>((const float4*)Wv, (uint2*)wvh, (uint2*)wvl, nw4);
    split_arr<<<(nw4 + 255) / 256, 256>>>((const float4*)Wo, (uint2*)woh, (uint2*)wol, nw4);
    split_arr<<<(nwff4 + 255) / 256, 256>>>((const float4*)Wfc, (uint2*)wfh, (uint2*)wfl, nwff4);
    split_arr<<<(nwff4 + 255) / 256, 256>>>((const float4*)Wp, (uint2*)wph, (uint2*)wpl, nwff4);

    // prologue
    scan_levels<<<1, S_LEN>>>(levels, gcpad);
    build_mask<<<S_LEN, 256>>>(levels, sample_i, gcpad, gmask);
    rope_table<<<S_LEN, 32>>>(gcos, gsin);
    rms_rows<<<S_LEN, 256>>>(x_in, gx);
    cudaMemcpyAsync(gx0, gx, (size_t)S_LEN * D_MOD * sizeof(float), cudaMemcpyDeviceToDevice);

    for (int i = 0; i < N_LAYERS; ++i) {
        size_t woff = (size_t)i * D_MOD * D_MOD;
        size_t foff = (size_t)i * D_FF * D_MOD;

        mix_rms<<<S_LEN, 256>>>(gx, gx0, lambdas, i, gxl, xnh, xnl);

        // fused QKV (z selects B/C)
        {
            dim3 grid(D_MOD / 128, S_LEN / 128, 3);
            gemm_bf16<<<grid, 256, GEMM_SMEM>>>(
                xnh, xnl,
                wqh + woff, wql + woff, wkh + woff, wkl + woff, wvh + woff, wvl + woff,
                gq, gk, gv, nullptr, nullptr, D_MOD, D_MOD, 0);
        }

        v_blend<<<(S_LEN * D_MOD / 4) / 256, 256>>>(gv, gv1, lamb, i);
        qk_rms_rope<<<(S_LEN * N_HEADS) / 8, 256>>>(gq, gk, gcos, gsin);

        flash_attn<<<dim3(S_LEN / 128, N_HEADS), 256, FLASH_SMEM>>>(gq, gk, gv, gmask, yh, yl);

        // x = xl + y @ Wo^T  (split-K=4 + fused reduce)
        {
            dim3 grid(D_MOD / 128, S_LEN / 128, 4);
            gemm_bf16<<<grid, 256, GEMM_SMEM>>>(
                yh, yl,
                woh + woff, wol + woff, woh + woff, wol + woff, woh + woff, wol + woff,
                gpart, gpart, gpart, nullptr, nullptr, D_MOD, D_MOD, 4);
            reduce4k<<<(n4 + 255) / 256, 256>>>((const float4*)gpart, (const float4*)gxl,
                                                (float4*)gx, n4);
        }

        // MLP
        rms_b<<<S_LEN, 256>>>(gx, xnh, xnl);
        {
            dim3 grid(D_FF / 128, S_LEN / 128, 1);
            gemm_bf16<<<grid, 256, GEMM_SMEM>>>(
                xnh, xnl,
                wfh + foff, wfl + foff, wfh + foff, wfl + foff, wfh + foff, wfl + foff,
                nullptr, nullptr, nullptr, hh, hl, D_FF, D_MOD, 2);
        }
        // x = x + h @ Wp^T  (split-K=4 over K=4096)
        {
            dim3 grid(D_MOD / 128, S_LEN / 128, 4);
            gemm_bf16<<<grid, 256, GEMM_SMEM>>>(
                hh, hl,
                wph + foff, wpl + foff, wph + foff, wpl + foff, wph + foff, wpl + foff,
                gpart, gpart, gpart, nullptr, nullptr, D_MOD, D_FF, 4);
            reduce4k<<<(n4 + 255) / 256, 256>>>((const float4*)gpart, (const float4*)gx,
                                                (float4*)gx, n4);
        }
    }

    rms_rows<<<S_LEN, 256>>>(gx, out);
}

// round 12
// speedup vs baseline: 1.1763x; 1.1763x over previous
#include <cuda_runtime.h>
#include <cuda_bf16.h>
#include <math.h>
#include <stdint.h>

#define S_LEN   1024
#define D_MOD   1024
#define N_HEADS 16
#define HEAD_D  64
#define D_FF    4096
#define N_LAYERS 6
#define EPSF    1.1920929e-07f

// ---------------- scratch (static device globals: no allocation) ----------------
__device__ float g_x [S_LEN*D_MOD];
__device__ float g_x0[S_LEN*D_MOD];
__device__ float g_xl[S_LEN*D_MOD];
__device__ float g_xn[S_LEN*D_MOD];
__device__ float g_q [S_LEN*D_MOD];
__device__ float g_k [S_LEN*D_MOD];
__device__ float g_v [S_LEN*D_MOD];
__device__ float g_v1[S_LEN*D_MOD];
__device__ float g_y [S_LEN*D_MOD];
__device__ float g_h [S_LEN*D_FF];
__device__ float g_part[4*S_LEN*D_MOD];
__device__ float g_mbuf[2*N_HEADS*S_LEN];
__device__ float g_lbuf[2*N_HEADS*S_LEN];
__device__ unsigned char g_maskbuf[S_LEN*S_LEN];
__device__ float g_cosb[S_LEN*32];
__device__ float g_sinb[S_LEN*32];
__device__ int   g_cpad[S_LEN+1];

// ---------------- helpers ----------------
__device__ __forceinline__ uint32_t smem_u32(const void* p) {
    uint32_t a;
    asm("{ .reg .u64 t; cvta.to.shared.u64 t, %1; cvt.u32.u64 %0, t; }" : "=r"(a) : "l"(p));
    return a;
}

#define LDMATRIX_X4(r0, r1, r2, r3, addr) \
    asm volatile("ldmatrix.sync.aligned.m8n8.x4.shared.b16 {%0,%1,%2,%3}, [%4];" \
                 : "=r"(r0), "=r"(r1), "=r"(r2), "=r"(r3) : "r"(addr))

#define MMA_BF16(c, a, b) \
    asm volatile("mma.sync.aligned.m16n8k16.row.col.f32.bf16.bf16.f32 " \
                 "{%0,%1,%2,%3}, {%4,%5,%6,%7}, {%8,%9}, {%0,%1,%2,%3};" \
                 : "+f"((c)[0]), "+f"((c)[1]), "+f"((c)[2]), "+f"((c)[3]) \
                 : "r"((a)[0]), "r"((a)[1]), "r"((a)[2]), "r"((a)[3]), \
                   "r"((b)[0]), "r"((b)[1]))

__device__ __forceinline__ uint32_t bf2u(__nv_bfloat162 h) {
    return *reinterpret_cast<uint32_t*>(&h);
}

__device__ __forceinline__ void split4(float4 v, uint2& hi, uint2& lo) {
    __nv_bfloat162 h01 = __floats2bfloat162_rn(v.x, v.y);
    __nv_bfloat162 h23 = __floats2bfloat162_rn(v.z, v.w);
    float lx = v.x - __low2float(h01);
    float ly = v.y - __high2float(h01);
    float lz = v.z - __low2float(h23);
    float lw = v.w - __high2float(h23);
    hi = make_uint2(bf2u(h01), bf2u(h23));
    lo = make_uint2(bf2u(__floats2bfloat162_rn(lx, ly)), bf2u(__floats2bfloat162_rn(lz, lw)));
}

// ---------------- reductions ----------------
__device__ __forceinline__ float block_sum(float v) {
    __shared__ float sh[32];
    int lane = threadIdx.x & 31, wid = threadIdx.x >> 5;
    #pragma unroll
    for (int o = 16; o; o >>= 1) v += __shfl_xor_sync(0xffffffffu, v, o);
    if (lane == 0) sh[wid] = v;
    __syncthreads();
    int nw = (blockDim.x + 31) >> 5;
    v = (lane < nw) ? sh[lane] : 0.f;
    #pragma unroll
    for (int o = 16; o; o >>= 1) v += __shfl_xor_sync(0xffffffffu, v, o);
    __syncthreads();
    return v;
}

// ---------------- setup kernels ----------------
__global__ void scan_levels(const int* __restrict__ levels, int* __restrict__ cpad) {
    __shared__ int sh[S_LEN];
    int t = threadIdx.x;
    sh[t] = (levels[t] == 0) ? 1 : 0;
    __syncthreads();
    for (int o = 1; o < S_LEN; o <<= 1) {
        int add = (t >= o) ? sh[t - o] : 0;
        __syncthreads();
        sh[t] += add;
        __syncthreads();
    }
    if (t == 0) cpad[0] = 0;
    cpad[t + 1] = sh[t];
}

__global__ void build_mask(const int* __restrict__ levels, const int* __restrict__ sample_idx,
                           const int* __restrict__ cpad, unsigned char* __restrict__ mask) {
    int i = blockIdx.x;
    int si = sample_idx[i];
    int ci = cpad[i];
    for (int j = threadIdx.x; j < S_LEN; j += blockDim.x) {
        bool causal = (i >= j);
        bool same   = (si == sample_idx[j]);
        int  cnt    = ci - cpad[j + 1];
        bool markov = (levels[j] == 0) && (cnt > 0);
        mask[(size_t)i * S_LEN + j] = (causal && same && !markov) ? 1 : 0;
    }
}

__global__ void rope_table(float* __restrict__ cosb, float* __restrict__ sinb) {
    int s = blockIdx.x;
    int e = threadIdx.x;
    float inv = powf(10000.f, -((float)e) / 32.f);
    float fr  = (float)s * inv;
    cosb[s * 32 + e] = cosf(fr);
    sinb[s * 32 + e] = sinf(fr);
}

// out = res + p0 + p1 + p2 + p3 (deterministic order)
__global__ void reduce4k(const float4* __restrict__ part, const float4* __restrict__ res,
                         float4* __restrict__ out, int n4) {
    int i = blockIdx.x * blockDim.x + threadIdx.x;
    if (i >= n4) return;
    float4 a = part[i], b = part[i + n4], c = part[i + 2 * n4], d = part[i + 3 * n4];
    float4 r = res[i];
    out[i] = make_float4(r.x + a.x + b.x + c.x + d.x,
                         r.y + a.y + b.y + c.y + d.y,
                         r.z + a.z + b.z + c.z + d.z,
                         r.w + a.w + b.w + c.w + d.w);
}

// merge two flash phases: y = (O0 e0 + O1 e1) / (l0 e0 + l1 e1)
__global__ void combine_flash(const float4* __restrict__ O0, const float4* __restrict__ O1,
                              const float* __restrict__ mbuf, const float* __restrict__ lbuf,
                              float4* __restrict__ y) {
    int i = blockIdx.x * blockDim.x + threadIdx.x;   // over S*D/4
    int row  = i >> 8;            // 256 float4 per row
    int col4 = i & 255;
    int h    = col4 >> 4;         // 16 float4 per head
    float ma = mbuf[h * S_LEN + row];
    float la = lbuf[h * S_LEN + row];
    float mb = mbuf[(N_HEADS + h) * S_LEN + row];
    float lb = lbuf[(N_HEADS + h) * S_LEN + row];
    float m  = fmaxf(ma, mb);
    float ea = __expf(ma - m), eb = __expf(mb - m);
    float inv = 1.f / (la * ea + lb * eb);
    float4 a = O0[i], b = O1[i];
    y[i] = make_float4((a.x * ea + b.x * eb) * inv, (a.y * ea + b.y * eb) * inv,
                       (a.z * ea + b.z * eb) * inv, (a.w * ea + b.w * eb) * inv);
}

// ---------------- row-wise rms ----------------
__global__ void rms_rows(const float* __restrict__ in, float* __restrict__ out) {
    int row = blockIdx.x, tid = threadIdx.x;
    float4 a = ((const float4*)(in + (size_t)row * D_MOD))[tid];
    float ss = a.x*a.x + a.y*a.y + a.z*a.z + a.w*a.w;
    ss = block_sum(ss);
    float r = rsqrtf(ss * (1.f / D_MOD) + EPSF);
    ((float4*)(out + (size_t)row * D_MOD))[tid] = make_float4(a.x*r, a.y*r, a.z*r, a.w*r);
}

__global__ void mix_rms(const float* __restrict__ x, const float* __restrict__ x0,
                        const float* __restrict__ lambdas, int layer,
                        float* __restrict__ xl, float* __restrict__ xn) {
    int row = blockIdx.x, tid = threadIdx.x;
    float l0 = lambdas[2 * layer], l1 = lambdas[2 * layer + 1];
    float4 a = ((const float4*)(x  + (size_t)row * D_MOD))[tid];
    float4 b = ((const float4*)(x0 + (size_t)row * D_MOD))[tid];
    float4 m = make_float4(l0*a.x + l1*b.x, l0*a.y + l1*b.y, l0*a.z + l1*b.z, l0*a.w + l1*b.w);
    float ss = m.x*m.x + m.y*m.y + m.z*m.z + m.w*m.w;
    ss = block_sum(ss);
    float r = rsqrtf(ss * (1.f / D_MOD) + EPSF);
    ((float4*)(xl + (size_t)row * D_MOD))[tid] = m;
    ((float4*)(xn + (size_t)row * D_MOD))[tid] = make_float4(m.x*r, m.y*r, m.z*r, m.w*r);
}

// ================= split-bf16 HMMA GEMM (proven R9 version) =================
// epi: 0 = plain (z selects B/C for QKV), 1 = +Res, 2 = relu^2,
//      4 = split-K partial: z = K-slice (of 4), C0 is partial base [z][M][N]
#define GSK   40
#define GTILE (128 * GSK)
#define GEMM_SMEM (2 * 4 * GTILE * 2)

__global__ __launch_bounds__(256, 1)
void gemm_mma(const float* __restrict__ A,
              const float* __restrict__ B0, const float* __restrict__ B1,
              const float* __restrict__ B2,
              const float* __restrict__ Res,
              float* __restrict__ C0, float* __restrict__ C1, float* __restrict__ C2,
              int N, int K, int epi)
{
    const float* B = (blockIdx.z == 0) ? B0 : (blockIdx.z == 1) ? B1 : B2;
    float*       C = (blockIdx.z == 0) ? C0 : (blockIdx.z == 1) ? C1 : C2;

    extern __shared__ char smem[];
    uint32_t sbase = smem_u32(smem);

    int tid  = threadIdx.x;
    int wid  = tid >> 5;
    int lane = tid & 31;
    int wm   = wid & 3;
    int wn   = wid >> 2;

    int row0 = blockIdx.y * 128;
    int col0 = blockIdx.x * 128;
    int Ks    = (epi == 4) ? (K >> 2) : K;
    int kbase = (epi == 4) ? blockIdx.z * Ks : 0;
    int nch   = Ks >> 5;

    float acc[2][8][4];
    #pragma unroll
    for (int mi = 0; mi < 2; ++mi)
        #pragma unroll
        for (int ni = 0; ni < 8; ++ni)
            #pragma unroll
            for (int e = 0; e < 4; ++e) acc[mi][ni][e] = 0.f;

    auto tileoff = [&](int buf, int which) -> uint32_t {
        return (uint32_t)((buf * 4 + which) * GTILE * 2);
    };

    float4 av[4], bv[4];
    #pragma unroll
    for (int i = 0; i < 4; ++i) {
        int f = tid + i * 256;
        int r = f >> 3, c4 = f & 7;
        av[i] = *(const float4*)&A[(size_t)(row0 + r) * K + kbase + c4 * 4];
        bv[i] = *(const float4*)&B[(size_t)(col0 + r) * K + kbase + c4 * 4];
    }
    #pragma unroll
    for (int i = 0; i < 4; ++i) {
        int f = tid + i * 256;
        int r = f >> 3, c4 = f & 7;
        uint32_t off = (uint32_t)(r * GSK + c4 * 4) * 2;
        uint2 hi, lo;
        split4(av[i], hi, lo);
        *(uint2*)(smem + tileoff(0, 0) + off) = hi;
        *(uint2*)(smem + tileoff(0, 1) + off) = lo;
        split4(bv[i], hi, lo);
        *(uint2*)(smem + tileoff(0, 2) + off) = hi;
        *(uint2*)(smem + tileoff(0, 3) + off) = lo;
    }
    __syncthreads();

    int a_r = wm * 32 + (lane & 15);
    int a_c = (lane >> 4) * 8;
    int b_r = wn * 64 + ((lane >> 4) & 1) * 8 + (lane & 7);
    int b_c = ((lane >> 3) & 1) * 8;

    for (int c = 0; c < nch; ++c) {
        int buf = c & 1;
        if (c + 1 < nch) {
            int k0 = kbase + ((c + 1) << 5);
            #pragma unroll
            for (int i = 0; i < 4; ++i) {
                int f = tid + i * 256;
                int r = f >> 3, c4 = f & 7;
                av[i] = *(const float4*)&A[(size_t)(row0 + r) * K + k0 + c4 * 4];
                bv[i] = *(const float4*)&B[(size_t)(col0 + r) * K + k0 + c4 * 4];
            }
        }

        uint32_t tAhi = sbase + tileoff(buf, 0);
        uint32_t tAlo = sbase + tileoff(buf, 1);
        uint32_t tBhi = sbase + tileoff(buf, 2);
        uint32_t tBlo = sbase + tileoff(buf, 3);

        #pragma unroll
        for (int ks = 0; ks < 2; ++ks) {
            uint32_t a_hi[2][4], a_lo[2][4];
            #pragma unroll
            for (int mi = 0; mi < 2; ++mi) {
                uint32_t off = (uint32_t)((a_r + mi * 16) * GSK + ks * 16 + a_c) * 2;
                LDMATRIX_X4(a_hi[mi][0], a_hi[mi][1], a_hi[mi][2], a_hi[mi][3], tAhi + off);
                LDMATRIX_X4(a_lo[mi][0], a_lo[mi][1], a_lo[mi][2], a_lo[mi][3], tAlo + off);
            }
            uint32_t b_hi[8][2], b_lo[8][2];
            #pragma unroll
            for (int p = 0; p < 4; ++p) {
                uint32_t off = (uint32_t)((b_r + p * 16) * GSK + ks * 16 + b_c) * 2;
                LDMATRIX_X4(b_hi[2*p][0], b_hi[2*p][1], b_hi[2*p+1][0], b_hi[2*p+1][1], tBhi + off);
                LDMATRIX_X4(b_lo[2*p][0], b_lo[2*p][1], b_lo[2*p+1][0], b_lo[2*p+1][1], tBlo + off);
            }
            #pragma unroll
            for (int mi = 0; mi < 2; ++mi)
                #pragma unroll
                for (int ni = 0; ni < 8; ++ni) {
                    MMA_BF16(acc[mi][ni], a_hi[mi], b_hi[ni]);
                    MMA_BF16(acc[mi][ni], a_hi[mi], b_lo[ni]);
                    MMA_BF16(acc[mi][ni], a_lo[mi], b_hi[ni]);
                }
        }

        if (c + 1 < nch) {
            int nb = (c + 1) & 1;
            #pragma unroll
            for (int i = 0; i < 4; ++i) {
                int f = tid + i * 256;
                int r = f >> 3, c4 = f & 7;
                uint32_t off = (uint32_t)(r * GSK + c4 * 4) * 2;
                uint2 hi, lo;
                split4(av[i], hi, lo);
                *(uint2*)(smem + tileoff(nb, 0) + off) = hi;
                *(uint2*)(smem + tileoff(nb, 1) + off) = lo;
                split4(bv[i], hi, lo);
                *(uint2*)(smem + tileoff(nb, 2) + off) = hi;
                *(uint2*)(smem + tileoff(nb, 3) + off) = lo;
            }
        }
        __syncthreads();
    }

    if (epi == 4) {
        float* Cz = C0 + (size_t)blockIdx.z * S_LEN * N;
        #pragma unroll
        for (int mi = 0; mi < 2; ++mi)
            #pragma unroll
            for (int ni = 0; ni < 8; ++ni) {
                int row = row0 + wm * 32 + mi * 16 + (lane >> 2);
                int col = col0 + wn * 64 + ni * 8 + (lane & 3) * 2;
                *(float2*)&Cz[(size_t)row * N + col] =
                    make_float2(acc[mi][ni][0], acc[mi][ni][1]);
                *(float2*)&Cz[(size_t)(row + 8) * N + col] =
                    make_float2(acc[mi][ni][2], acc[mi][ni][3]);
            }
        return;
    }

    #pragma unroll
    for (int mi = 0; mi < 2; ++mi) {
        #pragma unroll
        for (int ni = 0; ni < 8; ++ni) {
            int row = row0 + wm * 32 + mi * 16 + (lane >> 2);
            int col = col0 + wn * 64 + ni * 8 + (lane & 3) * 2;
            #pragma unroll
            for (int half = 0; half < 2; ++half) {
                int r = row + half * 8;
                float2 v = make_float2(acc[mi][ni][half * 2], acc[mi][ni][half * 2 + 1]);
                size_t gidx = (size_t)r * N + col;
                if (epi == 1) {
                    float2 rs = *(const float2*)&Res[gidx];
                    v.x += rs.x; v.y += rs.y;
                } else if (epi == 2) {
                    v.x = v.x > 0.f ? v.x * v.x : 0.f;
                    v.y = v.y > 0.f ? v.y * v.y : 0.f;
                }
                *(float2*)&C[gidx] = v;
            }
        }
    }
}

// ---------------- value residual blend ----------------
__global__ void v_blend(float* __restrict__ v, float* __restrict__ v1,
                        const float* __restrict__ lamb, int layer) {
    int i = blockIdx.x * blockDim.x + threadIdx.x;
    float lm = lamb[layer];
    float4* v4  = (float4*)v;
    float4* v14 = (float4*)v1;
    float4 a = v4[i];
    float4 b;
    if (layer == 0) { v14[i] = a; b = a; } else { b = v14[i]; }
    float om = 1.f - lm;
    v4[i] = make_float4(om*a.x + lm*b.x, om*a.y + lm*b.y, om*a.z + lm*b.z, om*a.w + lm*b.w);
}

// ---------------- per-head rms + rope on q and k ----------------
__global__ void qk_rms_rope(float* __restrict__ qb, float* __restrict__ kb,
                            const float* __restrict__ cosb, const float* __restrict__ sinb) {
    int pair = blockIdx.x * 8 + (threadIdx.x >> 5);
    int lane = threadIdx.x & 31;
    int s = pair >> 4;
    int h = pair & 15;
    float c  = cosb[s * 32 + lane];
    float si = sinb[s * 32 + lane];
    float* bufs[2] = { qb, kb };
    #pragma unroll
    for (int b = 0; b < 2; ++b) {
        float* p = bufs[b] + (size_t)s * D_MOD + h * HEAD_D;
        float x1 = p[lane];
        float x2 = p[lane + 32];
        float ss = x1 * x1 + x2 * x2;
        #pragma unroll
        for (int o = 16; o; o >>= 1) ss += __shfl_xor_sync(0xffffffffu, ss, o);
        float r = rsqrtf(ss * (1.f / HEAD_D) + EPSF);
        x1 *= r; x2 *= r;
        p[lane]      =  x1 * c  + x2 * si;
        p[lane + 32] = -x1 * si + x2 * c;
    }
}

// ================= fused flash attention, even/odd k-phase split =================
// grid (8 q-blocks, 16 heads, 2 phases); phase z handles kb = z, z+2, ...
// Emits UNNORMALIZED O partials + per-row (m, l); combine_flash merges.
#define FQS 72
#define FVS 136
#define OFF_QHI 0
#define OFF_QLO (128*FQS*2)
#define OFF_KHI (2*128*FQS*2)
#define OFF_KLO (3*128*FQS*2)
#define OFF_VHI (4*128*FQS*2)
#define OFF_VLO (OFF_VHI + 64*FVS*2)
#define OFF_MSK (OFF_VLO + 64*FVS*2)
#define FLASH_SMEM (OFF_MSK + 128*128)

__global__ __launch_bounds__(256, 1)
void flash_attn(const float* __restrict__ q, const float* __restrict__ k,
                const float* __restrict__ v, const unsigned char* __restrict__ mask,
                float* __restrict__ Opart, float* __restrict__ mbuf,
                float* __restrict__ lbuf)
{
    extern __shared__ char fs[];
    uint32_t sb = smem_u32(fs);

    int qb    = blockIdx.x;
    int h     = blockIdx.y;
    int phase = blockIdx.z;
    int q0 = qb * 128;
    int tid = threadIdx.x, lane = tid & 31, w = tid >> 5;

    #pragma unroll
    for (int i = 0; i < 8; ++i) {
        int f = tid + i * 256;
        int r = f >> 4, c4 = f & 15;
        float4 a = *(const float4*)&q[(size_t)(q0 + r) * D_MOD + h * HEAD_D + c4 * 4];
        uint2 hi, lo;
        split4(a, hi, lo);
        uint32_t off = (uint32_t)(r * FQS + c4 * 4) * 2;
        *(uint2*)(fs + OFF_QHI + off) = hi;
        *(uint2*)(fs + OFF_QLO + off) = lo;
    }

    float m0 = -3.4e38f, m1 = -3.4e38f, l0 = 0.f, l1 = 0.f;
    float oacc[8][4];
    #pragma unroll
    for (int nj = 0; nj < 8; ++nj)
        #pragma unroll
        for (int e = 0; e < 4; ++e) oacc[nj][e] = 0.f;

    int aq_off = (w * 16 + (lane & 15)) * FQS + (lane >> 4) * 8;
    int bk_r   = ((lane >> 4) & 1) * 8 + (lane & 7);
    int bk_c   = ((lane >> 3) & 1) * 8;
    int rowm   = w * 16 + (lane >> 2);

    for (int kb = phase; kb <= qb; kb += 2) {
        if (kb > phase) __syncthreads();
        #pragma unroll
        for (int i = 0; i < 8; ++i) {
            int f = tid + i * 256;
            int r = f >> 4, c4 = f & 15;
            float4 a = *(const float4*)&k[(size_t)(kb * 128 + r) * D_MOD + h * HEAD_D + c4 * 4];
            uint2 hi, lo;
            split4(a, hi, lo);
            uint32_t off = (uint32_t)(r * FQS + c4 * 4) * 2;
            *(uint2*)(fs + OFF_KHI + off) = hi;
            *(uint2*)(fs + OFF_KLO + off) = lo;

            float4 b = *(const float4*)&v[(size_t)(kb * 128 + r) * D_MOD + h * HEAD_D + c4 * 4];
            float bb[4] = { b.x, b.y, b.z, b.w };
            #pragma unroll
            for (int j = 0; j < 4; ++j) {
                __nv_bfloat16 hb = __float2bfloat16_rn(bb[j]);
                __nv_bfloat16 lb = __float2bfloat16_rn(bb[j] - __bfloat162float(hb));
                uint32_t to = (uint32_t)((c4 * 4 + j) * FVS + r) * 2;
                *(__nv_bfloat16*)(fs + OFF_VHI + to) = hb;
                *(__nv_bfloat16*)(fs + OFF_VLO + to) = lb;
            }
        }
        #pragma unroll
        for (int i = 0; i < 4; ++i) {
            int idx = tid + i * 256;
            int r = idx >> 3, c16 = idx & 7;
            uint4 mm = *(const uint4*)&mask[(size_t)(q0 + r) * S_LEN + kb * 128 + c16 * 16];
            *(uint4*)(fs + OFF_MSK + r * 128 + c16 * 16) = mm;
        }
        __syncthreads();

        float sacc[16][4];
        #pragma unroll
        for (int nf = 0; nf < 16; ++nf)
            #pragma unroll
            for (int e = 0; e < 4; ++e) sacc[nf][e] = 0.f;

        #pragma unroll
        for (int kc = 0; kc < 4; ++kc) {
            uint32_t ah[4], al[4];
            uint32_t aoff = (uint32_t)(aq_off + kc * 16) * 2;
            LDMATRIX_X4(ah[0], ah[1], ah[2], ah[3], sb + OFF_QHI + aoff);
            LDMATRIX_X4(al[0], al[1], al[2], al[3], sb + OFF_QLO + aoff);
            #pragma unroll
            for (int np = 0; np < 8; ++np) {
                uint32_t bh[2][2], bl[2][2];
                uint32_t boff = (uint32_t)((bk_r + np * 16) * FQS + bk_c + kc * 16) * 2;
                LDMATRIX_X4(bh[0][0], bh[0][1], bh[1][0], bh[1][1], sb + OFF_KHI + boff);
                LDMATRIX_X4(bl[0][0], bl[0][1], bl[1][0], bl[1][1], sb + OFF_KLO + boff);
                #pragma unroll
                for (int u = 0; u < 2; ++u) {
                    MMA_BF16(sacc[2*np+u], ah, bh[u]);
                    MMA_BF16(sacc[2*np+u], ah, bl[u]);
                    MMA_BF16(sacc[2*np+u], al, bh[u]);
                }
            }
        }

        float rmax0 = -3.4e38f, rmax1 = -3.4e38f;
        #pragma unroll
        for (int nf = 0; nf < 16; ++nf) {
            int colp = nf * 8 + (lane & 3) * 2;
            unsigned short mm0 = *(const unsigned short*)(fs + OFF_MSK + rowm * 128 + colp);
            unsigned short mm1 = *(const unsigned short*)(fs + OFF_MSK + (rowm + 8) * 128 + colp);
            sacc[nf][0] = (mm0 & 0xff)   ? sacc[nf][0] * 0.125f : -1e30f;
            sacc[nf][1] = (mm0 & 0xff00) ? sacc[nf][1] * 0.125f : -1e30f;
            sacc[nf][2] = (mm1 & 0xff)   ? sacc[nf][2] * 0.125f : -1e30f;
            sacc[nf][3] = (mm1 & 0xff00) ? sacc[nf][3] * 0.125f : -1e30f;
            rmax0 = fmaxf(rmax0, fmaxf(sacc[nf][0], sacc[nf][1]));
            rmax1 = fmaxf(rmax1, fmaxf(sacc[nf][2], sacc[nf][3]));
        }
        rmax0 = fmaxf(rmax0, __shfl_xor_sync(0xffffffffu, rmax0, 1));
        rmax0 = fmaxf(rmax0, __shfl_xor_sync(0xffffffffu, rmax0, 2));
        rmax1 = fmaxf(rmax1, __shfl_xor_sync(0xffffffffu, rmax1, 1));
        rmax1 = fmaxf(rmax1, __shfl_xor_sync(0xffffffffu, rmax1, 2));

        float mn0 = fmaxf(m0, rmax0), mn1 = fmaxf(m1, rmax1);
        float sc0 = __expf(m0 - mn0), sc1 = __expf(m1 - mn1);
        float sum0 = 0.f, sum1 = 0.f;
        #pragma unroll
        for (int nf = 0; nf < 16; ++nf) {
            sacc[nf][0] = __expf(sacc[nf][0] - mn0);
            sacc[nf][1] = __expf(sacc[nf][1] - mn0);
            sacc[nf][2] = __expf(sacc[nf][2] - mn1);
            sacc[nf][3] = __expf(sacc[nf][3] - mn1);
            sum0 += sacc[nf][0] + sacc[nf][1];
            sum1 += sacc[nf][2] + sacc[nf][3];
        }
        sum0 += __shfl_xor_sync(0xffffffffu, sum0, 1);
        sum0 += __shfl_xor_sync(0xffffffffu, sum0, 2);
        sum1 += __shfl_xor_sync(0xffffffffu, sum1, 1);
        sum1 += __shfl_xor_sync(0xffffffffu, sum1, 2);
        l0 = l0 * sc0 + sum0;
        l1 = l1 * sc1 + sum1;
        m0 = mn0; m1 = mn1;
        #pragma unroll
        for (int nj = 0; nj < 8; ++nj) {
            oacc[nj][0] *= sc0; oacc[nj][1] *= sc0;
            oacc[nj][2] *= sc1; oacc[nj][3] *= sc1;
        }

        #pragma unroll
        for (int kc = 0; kc < 8; ++kc) {
            uint32_t ph[4], pl[4];
            #pragma unroll
            for (int u = 0; u < 2; ++u) {
                float p0 = sacc[2*kc + u][0], p1 = sacc[2*kc + u][1];
                float p2 = sacc[2*kc + u][2], p3 = sacc[2*kc + u][3];
                __nv_bfloat162 h01 = __floats2bfloat162_rn(p0, p1);
                __nv_bfloat162 h23 = __floats2bfloat162_rn(p2, p3);
                ph[u * 2 + 0] = bf2u(h01);
                ph[u * 2 + 1] = bf2u(h23);
                pl[u * 2 + 0] = bf2u(__floats2bfloat162_rn(p0 - __low2float(h01), p1 - __high2float(h01)));
                pl[u * 2 + 1] = bf2u(__floats2bfloat162_rn(p2 - __low2float(h23), p3 - __high2float(h23)));
            }
            uint32_t ah[4] = { ph[0], ph[1], ph[2], ph[3] };
            uint32_t al[4] = { pl[0], pl[1], pl[2], pl[3] };
            #pragma unroll
            for (int np = 0; np < 4; ++np) {
                uint32_t bh[2][2], bl[2][2];
                uint32_t boff = (uint32_t)((bk_r + np * 16) * FVS + bk_c + kc * 16) * 2;
                LDMATRIX_X4(bh[0][0], bh[0][1], bh[1][0], bh[1][1], sb + OFF_VHI + boff);
                LDMATRIX_X4(bl[0][0], bl[0][1], bl[1][0], bl[1][1], sb + OFF_VLO + boff);
                #pragma unroll
                for (int u = 0; u < 2; ++u) {
                    MMA_BF16(oacc[2*np+u], ah, bh[u]);
                    MMA_BF16(oacc[2*np+u], ah, bl[u]);
                    MMA_BF16(oacc[2*np+u], al, bh[u]);
                }
            }
        }
    }

    // ---- epilogue: store UNNORMALIZED O partial + (m, l) per row ----
    float* Op = Opart + (size_t)phase * S_LEN * D_MOD;
    #pragma unroll
    for (int nj = 0; nj < 8; ++nj) {
        int row = q0 + rowm;
        int col = h * HEAD_D + nj * 8 + (lane & 3) * 2;
        *(float2*)&Op[(size_t)row * D_MOD + col] = make_float2(oacc[nj][0], oacc[nj][1]);
        *(float2*)&Op[(size_t)(row + 8) * D_MOD + col] = make_float2(oacc[nj][2], oacc[nj][3]);
    }
    if ((lane & 3) == 0) {
        int base = (phase * N_HEADS + h) * S_LEN + q0;
        mbuf[base + rowm]     = m0;
        lbuf[base + rowm]     = l0;
        mbuf[base + rowm + 8] = m1;
        lbuf[base + rowm + 8] = l1;
    }
}

// ---------------- host ----------------
extern "C" void kernel_launch(void* const* d_in, const int* in_sizes, int n_in,
                              void* d_out, int out_size) {
    const float* x_in     = (const float*)d_in[0];
    const float* Wq       = (const float*)d_in[1];
    const float* Wk       = (const float*)d_in[2];
    const float* Wv       = (const float*)d_in[3];
    const float* Wo       = (const float*)d_in[4];
    const float* lamb     = (const float*)d_in[5];
    const float* lambdas  = (const float*)d_in[6];
    const float* Wfc      = (const float*)d_in[7];
    const float* Wp       = (const float*)d_in[8];
    const int*   levels   = (const int*)d_in[9];
    const int*   sample_i = (const int*)d_in[10];
    float* out = (float*)d_out;

    cudaFuncSetAttribute(gemm_mma, cudaFuncAttributeMaxDynamicSharedMemorySize, GEMM_SMEM);
    cudaFuncSetAttribute(flash_attn, cudaFuncAttributeMaxDynamicSharedMemorySize, FLASH_SMEM);

    float *gx, *gx0, *gxl, *gxn, *gq, *gk, *gv, *gv1, *gy, *gh, *gpart, *gcos, *gsin;
    float *gmbuf, *glbuf;
    unsigned char* gmask;
    int* gcpad;
    cudaGetSymbolAddress((void**)&gx,    g_x);
    cudaGetSymbolAddress((void**)&gx0,   g_x0);
    cudaGetSymbolAddress((void**)&gxl,   g_xl);
    cudaGetSymbolAddress((void**)&gxn,   g_xn);
    cudaGetSymbolAddress((void**)&gq,    g_q);
    cudaGetSymbolAddress((void**)&gk,    g_k);
    cudaGetSymbolAddress((void**)&gv,    g_v);
    cudaGetSymbolAddress((void**)&gv1,   g_v1);
    cudaGetSymbolAddress((void**)&gy,    g_y);
    cudaGetSymbolAddress((void**)&gh,    g_h);
    cudaGetSymbolAddress((void**)&gpart, g_part);
    cudaGetSymbolAddress((void**)&gmbuf, g_mbuf);
    cudaGetSymbolAddress((void**)&glbuf, g_lbuf);
    cudaGetSymbolAddress((void**)&gmask, g_maskbuf);
    cudaGetSymbolAddress((void**)&gcos,  g_cosb);
    cudaGetSymbolAddress((void**)&gsin,  g_sinb);
    cudaGetSymbolAddress((void**)&gcpad, g_cpad);

    const int n4 = S_LEN * D_MOD / 4;

    // prologue
    scan_levels<<<1, S_LEN>>>(levels, gcpad);
    build_mask<<<S_LEN, 256>>>(levels, sample_i, gcpad, gmask);
    rope_table<<<S_LEN, 32>>>(gcos, gsin);
    rms_rows<<<S_LEN, 256>>>(x_in, gx);
    cudaMemcpyAsync(gx0, gx, (size_t)S_LEN * D_MOD * sizeof(float), cudaMemcpyDeviceToDevice);

    for (int i = 0; i < N_LAYERS; ++i) {
        const float* Wqi  = Wq  + (size_t)i * D_MOD * D_MOD;
        const float* Wki  = Wk  + (size_t)i * D_MOD * D_MOD;
        const float* Wvi  = Wv  + (size_t)i * D_MOD * D_MOD;
        const float* Woi  = Wo  + (size_t)i * D_MOD * D_MOD;
        const float* Wfci = Wfc + (size_t)i * D_FF  * D_MOD;
        const float* Wpi  = Wp  + (size_t)i * D_MOD * D_FF;

        mix_rms<<<S_LEN, 256>>>(gx, gx0, lambdas, i, gxl, gxn);

        // fused QKV (z selects B/C)
        {
            dim3 grid(D_MOD / 128, S_LEN / 128, 3);
            gemm_mma<<<grid, 256, GEMM_SMEM>>>(gxn, Wqi, Wki, Wvi, nullptr,
                                               gq, gk, gv, D_MOD, D_MOD, 0);
        }

        v_blend<<<(S_LEN * D_MOD / 4) / 256, 256>>>(gv, gv1, lamb, i);
        qk_rms_rope<<<(S_LEN * N_HEADS) / 8, 256>>>(gq, gk, gcos, gsin);

        // flash attention: even/odd k-phase split + combine
        flash_attn<<<dim3(S_LEN / 128, N_HEADS, 2), 256, FLASH_SMEM>>>(
            gq, gk, gv, gmask, gpart, gmbuf, glbuf);
        combine_flash<<<n4 / 256, 256>>>((const float4*)gpart,
                                         (const float4*)(gpart + (size_t)S_LEN * D_MOD),
                                         gmbuf, glbuf, (float4*)gy);

        // x = xl + y @ Wo^T  (split-K=4 + fused reduce)
        {
            dim3 grid(D_MOD / 128, S_LEN / 128, 4);
            gemm_mma<<<grid, 256, GEMM_SMEM>>>(gy, Woi, Woi, Woi, nullptr,
                                               gpart, gpart, gpart, D_MOD, D_MOD, 4);
            reduce4k<<<(n4 + 255) / 256, 256>>>((const float4*)gpart, (const float4*)gxl,
                                                (float4*)gx, n4);
        }

        // MLP
        rms_rows<<<S_LEN, 256>>>(gx, gxn);
        {
            dim3 grid(D_FF / 128, S_LEN / 128, 1);
            gemm_mma<<<grid, 256, GEMM_SMEM>>>(gxn, Wfci, Wfci, Wfci, nullptr,
                                               gh, gh, gh, D_FF, D_MOD, 2);
        }
        // x = x + h @ Wp^T  (split-K=4 over K=4096)
        {
            dim3 grid(D_MOD / 128, S_LEN / 128, 4);
            gemm_mma<<<grid, 256, GEMM_SMEM>>>(gh, Wpi, Wpi, Wpi, nullptr,
                                               gpart, gpart, gpart, D_MOD, D_FF, 4);
            reduce4k<<<(n4 + 255) / 256, 256>>>((const float4*)gpart, (const float4*)gx,
                                                (float4*)gx, n4);
        }
    }

    rms_rows<<<S_LEN, 256>>>(gx, out);
}